// round 13
// baseline (speedup 1.0000x reference)
#include <cuda_runtime.h>
#include <cstdint>

#define BB 256
#define CC 768
#define LL 256
#define PP 3
#define MINUS_F (-100.0f)
#define BIAS_F  (-200.0f)

#define ROWS_PER_BLOCK 64
#define NWARPS 8
#define ROWS_PER_WARP (ROWS_PER_BLOCK / NWARPS)   // 8
#define THREADS (NWARPS * 32)

// 4 blocks/SM (<=64 regs): R11's proven occupancy point, now with depth-2 prefetch.
__global__ __launch_bounds__(THREADS, 4) void piece_max_pool_kernel(
    const float* __restrict__ x,
    const int*   __restrict__ m32,   // int32 view of mask buffer (int32 or int64 data)
    float*       __restrict__ out)
{
    const int b    = blockIdx.x;
    const int c0   = blockIdx.y * ROWS_PER_BLOCK;
    const int tid  = threadIdx.x;
    const int warp = tid >> 5;
    const int lane = tid & 31;

    // ---- In-kernel dtype detection (single launch) ----
    //  int64 mask: odd int32 slots = high words == 0 (values in [0,3]).
    //  int32 mask: odd slots = 256 random values in 0..3 -> some nonzero.
    const int probe = m32[2 * tid + 1];
    const bool is64 = (__syncthreads_or(probe != 0) == 0);

    // ---- Per-lane mask values for this lane's 8 fixed L positions ----
    //   l = h*128 + lane*4 + j,  h in {0,1}, j in {0..3}
    int mv[8];
    const int base = b * LL;
    if (is64) {
#pragma unroll
        for (int h = 0; h < 2; ++h) {
            const int4* mp = reinterpret_cast<const int4*>(m32 + 2 * (base + h * 128));
            const int4 q0 = mp[2 * lane];
            const int4 q1 = mp[2 * lane + 1];
            mv[h * 4 + 0] = q0.x;  mv[h * 4 + 1] = q0.z;
            mv[h * 4 + 2] = q1.x;  mv[h * 4 + 3] = q1.z;
        }
    } else {
#pragma unroll
        for (int h = 0; h < 2; ++h) {
            const int4 q = reinterpret_cast<const int4*>(m32 + base + h * 128)[lane];
            mv[h * 4 + 0] = q.x;  mv[h * 4 + 1] = q.y;
            mv[h * 4 + 2] = q.z;  mv[h * 4 + 3] = q.w;
        }
    }

    // ---- Additive biases, computed once, reused across all 8 rows ----
    float bias0[8], bias1[8], bias2[8];
#pragma unroll
    for (int j = 0; j < 8; ++j) {
        bias0[j] = (mv[j] == 1) ? 0.0f : BIAS_F;
        bias1[j] = (mv[j] == 2) ? 0.0f : BIAS_F;
        bias2[j] = (mv[j] == 3) ? 0.0f : BIAS_F;
    }

    const int c_base = c0 + warp * ROWS_PER_WARP;
    const float* xrow = x + (size_t)(b * CC + c_base) * LL;
    float* const outb = out + (size_t)b * (PP * CC);

    // ---- Depth-2 software pipeline: 4 LDG.128 (2KB) in flight per warp ----
    float4 buf0[2], buf1[2];
    {
        const float4* p0 = reinterpret_cast<const float4*>(xrow);
        const float4* p1 = reinterpret_cast<const float4*>(xrow + LL);
        buf0[0] = __ldcs(p0 + lane);
        buf1[0] = __ldcs(p0 + lane + 32);
        buf0[1] = __ldcs(p1 + lane);
        buf1[1] = __ldcs(p1 + lane + 32);
    }

#pragma unroll
    for (int r = 0; r < ROWS_PER_WARP; ++r) {
        const float4 v0 = buf0[r & 1];
        const float4 v1 = buf1[r & 1];
        if (r < ROWS_PER_WARP - 2) {
            const float4* pn = reinterpret_cast<const float4*>(xrow + (size_t)(r + 2) * LL);
            buf0[r & 1] = __ldcs(pn + lane);
            buf1[r & 1] = __ldcs(pn + lane + 32);
        }

        float g  = -1e30f;
        float a0 = -1e30f, a1 = -1e30f, a2 = -1e30f;

        const float vv[8] = {v0.x, v0.y, v0.z, v0.w, v1.x, v1.y, v1.z, v1.w};
#pragma unroll
        for (int j = 0; j < 8; ++j) {
            const float v = vv[j];
            g  = fmaxf(g,  v);
            a0 = fmaxf(a0, v + bias0[j]);
            a1 = fmaxf(a1, v + bias1[j]);
            a2 = fmaxf(a2, v + bias2[j]);
        }

        // ---- Multi-value butterfly over {g,a0,a1,a2}: 7 SHFL total ----
        const bool up1 = lane & 1;
        {
            const float s0 = up1 ? g  : a1;
            const float s1 = up1 ? a0 : a2;
            const float r0 = __shfl_xor_sync(0xFFFFFFFFu, s0, 1);
            const float r1 = __shfl_xor_sync(0xFFFFFFFFu, s1, 1);
            const float k0 = up1 ? a1 : g;
            const float k1 = up1 ? a2 : a0;
            g  = fmaxf(k0, r0);
            a0 = fmaxf(k1, r1);
        }
        const bool up2 = lane & 2;
        float v = up2 ? a0 : g;
        {
            const float s = up2 ? g : a0;
            const float rr = __shfl_xor_sync(0xFFFFFFFFu, s, 2);
            v = fmaxf(v, rr);
        }
        v = fmaxf(v, __shfl_xor_sync(0xFFFFFFFFu, v, 4));
        v = fmaxf(v, __shfl_xor_sync(0xFFFFFFFFu, v, 8));
        v = fmaxf(v, __shfl_xor_sync(0xFFFFFFFFu, v, 16));

        // Mapping proven in R8: lane1 -> piece 1, lane2 -> piece 0, lane3 -> piece 2.
        const float g_row = __shfl_sync(0xFFFFFFFFu, v, 0);

        if (lane >= 1 && lane <= 3) {
            const int piece = (lane == 2) ? 0 : ((lane == 1) ? 1 : 2);
            outb[piece * CC + (c_base + r)] = fmaxf(v, g_row + MINUS_F);
        }
    }
}

extern "C" void kernel_launch(void* const* d_in, const int* in_sizes, int n_in,
                              void* d_out, int out_size)
{
    const float* x = (const float*)d_in[0];
    const int*   m = (const int*)d_in[1];   // int32 view of mask buffer
    float* out = (float*)d_out;

    dim3 grid(BB, CC / ROWS_PER_BLOCK);
    piece_max_pool_kernel<<<grid, THREADS>>>(x, m, out);
}

// round 15
// speedup vs baseline: 1.1231x; 1.1231x over previous
#include <cuda_runtime.h>
#include <cstdint>

#define BB 256
#define CC 768
#define LL 256
#define PP 3
#define MINUS_F (-100.0f)
#define BIAS_F  (-200.0f)

#define ROWS_PER_BLOCK 64
#define NWARPS 8
#define ROWS_PER_WARP (ROWS_PER_BLOCK / NWARPS)   // 8
#define THREADS (NWARPS * 32)

// Reduce {g, h0, h1, h2} across the warp (butterfly, 6 SHFL + 1).
// Returns reduced value; lane1 holds h1's max, lane2 h0's, lane3 h2's
// (mapping proven in R8).
__device__ __forceinline__ float butterfly4(float g, float h0, float h1, float h2,
                                            int lane)
{
    const bool up1 = lane & 1;
    const float s0 = up1 ? g  : h1;
    const float s1 = up1 ? h0 : h2;
    const float r0 = __shfl_xor_sync(0xFFFFFFFFu, s0, 1);
    const float r1 = __shfl_xor_sync(0xFFFFFFFFu, s1, 1);
    const float k0 = up1 ? h1 : g;
    const float k1 = up1 ? h2 : h0;
    const float m0 = fmaxf(k0, r0);
    const float m1 = fmaxf(k1, r1);

    const bool up2 = lane & 2;
    float v = up2 ? m1 : m0;
    const float s = up2 ? m0 : m1;
    v = fmaxf(v, __shfl_xor_sync(0xFFFFFFFFu, s, 2));

    v = fmaxf(v, __shfl_xor_sync(0xFFFFFFFFu, v, 4));
    v = fmaxf(v, __shfl_xor_sync(0xFFFFFFFFu, v, 8));
    v = fmaxf(v, __shfl_xor_sync(0xFFFFFFFFu, v, 16));
    return v;
}

__global__ __launch_bounds__(THREADS, 4) void piece_max_pool_kernel(
    const float* __restrict__ x,
    const int*   __restrict__ m32,   // int32 view of mask buffer (int32 or int64 data)
    float*       __restrict__ out)
{
    const int b    = blockIdx.x;
    const int c0   = blockIdx.y * ROWS_PER_BLOCK;
    const int tid  = threadIdx.x;
    const int warp = tid >> 5;
    const int lane = tid & 31;

    // ---- In-kernel dtype detection (single launch) ----
    //  int64 mask: odd int32 slots = high words == 0 (values in [0,3]).
    //  int32 mask: odd slots = 256 random values in 0..3 -> some nonzero.
    const int probe = m32[2 * tid + 1];
    const bool is64 = (__syncthreads_or(probe != 0) == 0);

    // ---- Per-lane mask values for this lane's 8 fixed L positions ----
    int mv[8];
    const int base = b * LL;
    if (is64) {
#pragma unroll
        for (int h = 0; h < 2; ++h) {
            const int4* mp = reinterpret_cast<const int4*>(m32 + 2 * (base + h * 128));
            const int4 q0 = mp[2 * lane];
            const int4 q1 = mp[2 * lane + 1];
            mv[h * 4 + 0] = q0.x;  mv[h * 4 + 1] = q0.z;
            mv[h * 4 + 2] = q1.x;  mv[h * 4 + 3] = q1.z;
        }
    } else {
#pragma unroll
        for (int h = 0; h < 2; ++h) {
            const int4 q = reinterpret_cast<const int4*>(m32 + base + h * 128)[lane];
            mv[h * 4 + 0] = q.x;  mv[h * 4 + 1] = q.y;
            mv[h * 4 + 2] = q.z;  mv[h * 4 + 3] = q.w;
        }
    }

    // ---- Additive biases, computed once, reused across all 8 rows ----
    float bias0[8], bias1[8], bias2[8];
#pragma unroll
    for (int j = 0; j < 8; ++j) {
        bias0[j] = (mv[j] == 1) ? 0.0f : BIAS_F;
        bias1[j] = (mv[j] == 2) ? 0.0f : BIAS_F;
        bias2[j] = (mv[j] == 3) ? 0.0f : BIAS_F;
    }

    const int c_base = c0 + warp * ROWS_PER_WARP;
    const float4* xp = reinterpret_cast<const float4*>(
        x + (size_t)(b * CC + c_base) * LL);   // row stride = LL/4 float4s
    float* const outb = out + (size_t)b * (PP * CC);

    // Prefetch pair 0 (rows 0,1): 4 LDG.128 = 2KB in flight. Plain scalars.
    float4 nA0 = __ldcs(xp + lane);
    float4 nA1 = __ldcs(xp + lane + 32);
    float4 nB0 = __ldcs(xp + lane + 64);
    float4 nB1 = __ldcs(xp + lane + 96);

#pragma unroll
    for (int pr = 0; pr < ROWS_PER_WARP / 2; ++pr) {
        const float4 vA0 = nA0, vA1 = nA1, vB0 = nB0, vB1 = nB1;
        if (pr < ROWS_PER_WARP / 2 - 1) {
            const int off = (2 * pr + 2) * (LL / 4);   // constant per unrolled iter
            nA0 = __ldcs(xp + off + lane);
            nA1 = __ldcs(xp + off + lane + 32);
            nB0 = __ldcs(xp + off + lane + 64);
            nB1 = __ldcs(xp + off + lane + 96);
        }

        // ---- Accumulate both rows (independent chains) ----
        float gA = -1e30f, a0A = -1e30f, a1A = -1e30f, a2A = -1e30f;
        float gB = -1e30f, a0B = -1e30f, a1B = -1e30f, a2B = -1e30f;

        const float vvA[8] = {vA0.x, vA0.y, vA0.z, vA0.w, vA1.x, vA1.y, vA1.z, vA1.w};
        const float vvB[8] = {vB0.x, vB0.y, vB0.z, vB0.w, vB1.x, vB1.y, vB1.z, vB1.w};
#pragma unroll
        for (int j = 0; j < 8; ++j) {
            const float va = vvA[j];
            gA  = fmaxf(gA,  va);
            a0A = fmaxf(a0A, va + bias0[j]);
            a1A = fmaxf(a1A, va + bias1[j]);
            a2A = fmaxf(a2A, va + bias2[j]);
            const float vb = vvB[j];
            gB  = fmaxf(gB,  vb);
            a0B = fmaxf(a0B, vb + bias0[j]);
            a1B = fmaxf(a1B, vb + bias1[j]);
            a2B = fmaxf(a2B, vb + bias2[j]);
        }

        // ---- Fold g per-lane: max distributes over the lane reduction, so
        // reducing h_p = max(a_p, g-100) gives max(max a_p, max g - 100)
        // directly — no post-reduction broadcast needed. ----
        const float gmA = gA + MINUS_F;
        const float gmB = gB + MINUS_F;
        const float vA = butterfly4(gA, fmaxf(a0A, gmA), fmaxf(a1A, gmA),
                                    fmaxf(a2A, gmA), lane);
        const float vB = butterfly4(gB, fmaxf(a0B, gmB), fmaxf(a1B, gmB),
                                    fmaxf(a2B, gmB), lane);

        if (lane >= 1 && lane <= 3) {
            const int piece = (lane == 2) ? 0 : ((lane == 1) ? 1 : 2);
            const int c = c_base + 2 * pr;
            outb[piece * CC + c]     = vA;
            outb[piece * CC + c + 1] = vB;
        }
    }
}

extern "C" void kernel_launch(void* const* d_in, const int* in_sizes, int n_in,
                              void* d_out, int out_size)
{
    const float* x = (const float*)d_in[0];
    const int*   m = (const int*)d_in[1];   // int32 view of mask buffer
    float* out = (float*)d_out;

    dim3 grid(BB, CC / ROWS_PER_BLOCK);
    piece_max_pool_kernel<<<grid, THREADS>>>(x, m, out);
}

// round 17
// speedup vs baseline: 1.1665x; 1.0387x over previous
#include <cuda_runtime.h>
#include <cstdint>

#define BB 256
#define CC 768
#define LL 256
#define PP 3
#define MINUS_F (-100.0f)
#define BIAS_F  (-200.0f)

#define ROWS_PER_BLOCK 32
#define NWARPS 8
#define ROWS_PER_WARP (ROWS_PER_BLOCK / NWARPS)   // 4
#define THREADS (NWARPS * 32)

// Reduce {g, h0, h1, h2} across the warp (butterfly, 7 SHFL).
// lane1 holds h1's max, lane2 h0's, lane3 h2's (mapping proven in R8).
__device__ __forceinline__ float butterfly4(float g, float h0, float h1, float h2,
                                            int lane)
{
    const bool up1 = lane & 1;
    const float s0 = up1 ? g  : h1;
    const float s1 = up1 ? h0 : h2;
    const float r0 = __shfl_xor_sync(0xFFFFFFFFu, s0, 1);
    const float r1 = __shfl_xor_sync(0xFFFFFFFFu, s1, 1);
    const float k0 = up1 ? h1 : g;
    const float k1 = up1 ? h2 : h0;
    const float m0 = fmaxf(k0, r0);
    const float m1 = fmaxf(k1, r1);

    const bool up2 = lane & 2;
    float v = up2 ? m1 : m0;
    const float s = up2 ? m0 : m1;
    v = fmaxf(v, __shfl_xor_sync(0xFFFFFFFFu, s, 2));

    v = fmaxf(v, __shfl_xor_sync(0xFFFFFFFFu, v, 4));
    v = fmaxf(v, __shfl_xor_sync(0xFFFFFFFFu, v, 8));
    v = fmaxf(v, __shfl_xor_sync(0xFFFFFFFFu, v, 16));
    return v;
}

__global__ __launch_bounds__(THREADS, 4) void piece_max_pool_kernel(
    const float* __restrict__ x,
    const int*   __restrict__ m32,   // int32 view of mask buffer (int32 or int64 data)
    float*       __restrict__ out)
{
    const int b    = blockIdx.x;
    const int c0   = blockIdx.y * ROWS_PER_BLOCK;
    const int tid  = threadIdx.x;
    const int warp = tid >> 5;
    const int lane = tid & 31;

    // ---- In-kernel dtype detection (single launch) ----
    //  int64 mask: odd int32 slots = high words == 0 (values in [0,3]).
    //  int32 mask: odd slots = 256 random values in 0..3 -> some nonzero.
    const int probe = m32[2 * tid + 1];
    const bool is64 = (__syncthreads_or(probe != 0) == 0);

    // ---- Per-lane mask values for this lane's 8 fixed L positions ----
    int mv[8];
    const int base = b * LL;
    if (is64) {
#pragma unroll
        for (int h = 0; h < 2; ++h) {
            const int4* mp = reinterpret_cast<const int4*>(m32 + 2 * (base + h * 128));
            const int4 q0 = mp[2 * lane];
            const int4 q1 = mp[2 * lane + 1];
            mv[h * 4 + 0] = q0.x;  mv[h * 4 + 1] = q0.z;
            mv[h * 4 + 2] = q1.x;  mv[h * 4 + 3] = q1.z;
        }
    } else {
#pragma unroll
        for (int h = 0; h < 2; ++h) {
            const int4 q = reinterpret_cast<const int4*>(m32 + base + h * 128)[lane];
            mv[h * 4 + 0] = q.x;  mv[h * 4 + 1] = q.y;
            mv[h * 4 + 2] = q.z;  mv[h * 4 + 3] = q.w;
        }
    }

    // ---- Additive biases, computed once per block ----
    float bias0[8], bias1[8], bias2[8];
#pragma unroll
    for (int j = 0; j < 8; ++j) {
        bias0[j] = (mv[j] == 1) ? 0.0f : BIAS_F;
        bias1[j] = (mv[j] == 2) ? 0.0f : BIAS_F;
        bias2[j] = (mv[j] == 3) ? 0.0f : BIAS_F;
    }

    const int c_base = c0 + warp * ROWS_PER_WARP;
    const float4* xp = reinterpret_cast<const float4*>(
        x + (size_t)(b * CC + c_base) * LL);   // row stride = LL/4 float4s
    float* const outb = out + (size_t)b * (PP * CC);

    // Prefetch pair 0 (rows 0,1): 4 LDG.128 = 2KB in flight. Plain scalars.
    float4 nA0 = __ldcs(xp + lane);
    float4 nA1 = __ldcs(xp + lane + 32);
    float4 nB0 = __ldcs(xp + lane + 64);
    float4 nB1 = __ldcs(xp + lane + 96);

#pragma unroll
    for (int pr = 0; pr < ROWS_PER_WARP / 2; ++pr) {
        const float4 vA0 = nA0, vA1 = nA1, vB0 = nB0, vB1 = nB1;
        if (pr < ROWS_PER_WARP / 2 - 1) {
            const int off = (2 * pr + 2) * (LL / 4);   // constant per unrolled iter
            nA0 = __ldcs(xp + off + lane);
            nA1 = __ldcs(xp + off + lane + 32);
            nB0 = __ldcs(xp + off + lane + 64);
            nB1 = __ldcs(xp + off + lane + 96);
        }

        // ---- Accumulate both rows (independent chains) ----
        float gA = -1e30f, a0A = -1e30f, a1A = -1e30f, a2A = -1e30f;
        float gB = -1e30f, a0B = -1e30f, a1B = -1e30f, a2B = -1e30f;

        const float vvA[8] = {vA0.x, vA0.y, vA0.z, vA0.w, vA1.x, vA1.y, vA1.z, vA1.w};
        const float vvB[8] = {vB0.x, vB0.y, vB0.z, vB0.w, vB1.x, vB1.y, vB1.z, vB1.w};
#pragma unroll
        for (int j = 0; j < 8; ++j) {
            const float va = vvA[j];
            gA  = fmaxf(gA,  va);
            a0A = fmaxf(a0A, va + bias0[j]);
            a1A = fmaxf(a1A, va + bias1[j]);
            a2A = fmaxf(a2A, va + bias2[j]);
            const float vb = vvB[j];
            gB  = fmaxf(gB,  vb);
            a0B = fmaxf(a0B, vb + bias0[j]);
            a1B = fmaxf(a1B, vb + bias1[j]);
            a2B = fmaxf(a2B, vb + bias2[j]);
        }

        // ---- Fold g per-lane (max distributes over lane reduction) ----
        const float gmA = gA + MINUS_F;
        const float gmB = gB + MINUS_F;
        const float vA = butterfly4(gA, fmaxf(a0A, gmA), fmaxf(a1A, gmA),
                                    fmaxf(a2A, gmA), lane);
        const float vB = butterfly4(gB, fmaxf(a0B, gmB), fmaxf(a1B, gmB),
                                    fmaxf(a2B, gmB), lane);

        if (lane >= 1 && lane <= 3) {
            const int piece = (lane == 2) ? 0 : ((lane == 1) ? 1 : 2);
            const int c = c_base + 2 * pr;
            outb[piece * CC + c]     = vA;
            outb[piece * CC + c + 1] = vB;
        }
    }
}

extern "C" void kernel_launch(void* const* d_in, const int* in_sizes, int n_in,
                              void* d_out, int out_size)
{
    const float* x = (const float*)d_in[0];
    const int*   m = (const int*)d_in[1];   // int32 view of mask buffer
    float* out = (float*)d_out;

    dim3 grid(BB, CC / ROWS_PER_BLOCK);   // 256 x 24 = 6144 CTAs
    piece_max_pool_kernel<<<grid, THREADS>>>(x, m, out);
}